// round 7
// baseline (speedup 1.0000x reference)
#include <cuda_runtime.h>
#include <math.h>
#include <stdint.h>

typedef unsigned long long ull;

#define B 64
#define H 1024
#define HY 256
#define F 64
#define IND 133
#define NSEQ 128
#define OUTD 123
#define GRID 148

// ---------------- persistent device state ----------------------------------
__device__ __align__(16) float g_h[H][B];
__device__ __align__(16) float g_c[H][B];
__device__ __align__(16) float g_hh[2][HY][B];
__device__ __align__(16) float g_ch[HY][B];
__device__ __align__(16) float g_z[3 * HY][B];
__device__ __align__(16) float g_ahp[4][4 * H][B];   // h@Wh split-K partials
__device__ __align__(16) float g_x[NSEQ][IND][B];
__device__ __align__(16) float g_axp[NSEQ][4 * H][B];   // precomputed x@Wx
__device__ __align__(16) float g_gxh[NSEQ][4 * HY][B];  // precomputed x@Wxh(x-rows)
__device__ __align__(16) float g_outs[NSEQ][H][B];
__device__ __align__(16) float g_dec[NSEQ][OUTD][B];
__device__ unsigned g_bar_count;
__device__ unsigned g_bar_gen;

__device__ __forceinline__ float sigf(float x) { return 1.0f / (1.0f + expf(-x)); }

__device__ __forceinline__ void fma2(ull& d, ull a, ull b) {
    asm("fma.rn.f32x2 %0, %1, %2, %0;" : "+l"(d) : "l"(a), "l"(b));
}
__device__ __forceinline__ ull mul2(ull a, ull b) {
    ull d; asm("mul.rn.f32x2 %0, %1, %2;" : "=l"(d) : "l"(a), "l"(b)); return d;
}
__device__ __forceinline__ ull add2(ull a, ull b) {
    ull d; asm("add.rn.f32x2 %0, %1, %2;" : "=l"(d) : "l"(a), "l"(b)); return d;
}
__device__ __forceinline__ ull pack2(float x, float y) {
    ull r; asm("mov.b64 %0, {%1, %2};" : "=l"(r) : "f"(x), "f"(y)); return r;
}

// ---------------- grid-wide barrier (all blocks co-resident) ----------------
__device__ __forceinline__ void grid_bar() {
    __syncthreads();
    if (threadIdx.x == 0) {
        unsigned gen = *(volatile unsigned*)&g_bar_gen;
        __threadfence();
        unsigned arr = atomicAdd(&g_bar_count, 1u);
        if (arr == GRID - 1) {
            *(volatile unsigned*)&g_bar_count = 0u;
            __threadfence();
            *(volatile unsigned*)&g_bar_gen = gen + 1u;
        } else {
            while (*(volatile unsigned*)&g_bar_gen == gen) {}
        }
        __threadfence();
    }
    __syncthreads();
}

// ---------------- GEMM tiles -------------------------------------------------
// 64-col tile, KT=16, arbitrary K (zero-padded tail). acc[c][2] = 4col x 4batch.
__device__ __forceinline__ void gemm_seg64(const float* __restrict__ A,
                                           const float* __restrict__ W,
                                           int K, int ldw, int colbase,
                                           float (*sA)[64], float (*sW)[64],
                                           ull (&acc)[4][2], int tid) {
    const int row = tid >> 4;
    const int q4  = (tid & 15) << 2;
    const int bg4 = (tid & 15) << 2;
    const int cg4 = (tid >> 4) << 2;
    const int nst = (K + 15) >> 4;
    const float4 f40 = make_float4(0.f, 0.f, 0.f, 0.f);

    float4 pa = (row < K) ? *(const float4*)(A + row * 64 + q4) : f40;
    float4 pw = (row < K) ? *(const float4*)(W + row * ldw + colbase + q4) : f40;

    for (int s = 0; s < nst; s++) {
        __syncthreads();
        *(float4*)(&sA[row][q4]) = pa;
        *(float4*)(&sW[row][q4]) = pw;
        __syncthreads();
        if (s + 1 < nst) {
            int kn = (s + 1) * 16 + row;
            pa = (kn < K) ? *(const float4*)(A + kn * 64 + q4) : f40;
            pw = (kn < K) ? *(const float4*)(W + kn * ldw + colbase + q4) : f40;
        }
#pragma unroll
        for (int k = 0; k < 16; k++) {
            ulonglong2 a = *(const ulonglong2*)(&sA[k][bg4]);
            float4 w = *(const float4*)(&sW[k][cg4]);
            ull w0 = pack2(w.x, w.x), w1 = pack2(w.y, w.y);
            ull w2 = pack2(w.z, w.z), w3 = pack2(w.w, w.w);
            fma2(acc[0][0], a.x, w0); fma2(acc[0][1], a.y, w0);
            fma2(acc[1][0], a.x, w1); fma2(acc[1][1], a.y, w1);
            fma2(acc[2][0], a.x, w2); fma2(acc[2][1], a.y, w2);
            fma2(acc[3][0], a.x, w3); fma2(acc[3][1], a.y, w3);
        }
    }
    __syncthreads();
}

// hyper 32-col tile (4 gates x 8 j), gate-strided W cols; K multiple of 16.
__device__ __forceinline__ void gemm_seg32h(const float* __restrict__ A,
                                            const float* __restrict__ W,
                                            int K, int jbase,
                                            float (*sA)[64], float (*sW)[32],
                                            ull (&acc)[2][2], int tid) {
    const int row = tid >> 4;
    const int q4  = (tid & 15) << 2;
    const int c2  = (tid & 15) << 1;
    const int bg4 = (tid & 15) << 2;
    const int cg  = tid >> 4;
    const int wcol = ((c2 >> 3) << 8) + jbase + (c2 & 7);
    const int nst = K >> 4;

    float4 pa = *(const float4*)(A + row * 64 + q4);
    float2 pw = *(const float2*)(W + row * 1024 + wcol);

    for (int s = 0; s < nst; s++) {
        __syncthreads();
        *(float4*)(&sA[row][q4]) = pa;
        *(float2*)(&sW[row][c2]) = pw;
        __syncthreads();
        if (s + 1 < nst) {
            int kn = (s + 1) * 16 + row;
            pa = *(const float4*)(A + kn * 64 + q4);
            pw = *(const float2*)(W + kn * 1024 + wcol);
        }
#pragma unroll
        for (int k = 0; k < 16; k++) {
            ulonglong2 a = *(const ulonglong2*)(&sA[k][bg4]);
            float2 w = *(const float2*)(&sW[k][cg * 2]);
            ull w0 = pack2(w.x, w.x), w1 = pack2(w.y, w.y);
            fma2(acc[0][0], a.x, w0); fma2(acc[0][1], a.y, w0);
            fma2(acc[1][0], a.x, w1); fma2(acc[1][1], a.y, w1);
        }
    }
    __syncthreads();
}

// 32 contiguous cols, fixed K=256, ldw=4096 (Wh split-K slice).
__device__ __forceinline__ void gemm_seg32w(const float* __restrict__ A,
                                            const float* __restrict__ W, int cb,
                                            float* sA, float* sW,
                                            ull (&acc)[4], int tid) {
    const int ar = tid >> 4, aq = (tid & 15) << 2;
    const bool wact = tid < 128;
    const int wr = tid >> 3, wq = (tid & 7) << 2;
    const int cg4 = (tid >> 5) << 2, bg2 = (tid & 31) << 1;
    float4 pa = *(const float4*)(A + ar * 64 + aq);
    float4 pw = make_float4(0.f, 0.f, 0.f, 0.f);
    if (wact) pw = *(const float4*)(W + wr * 4096 + cb + wq);
    for (int s = 0; s < 16; s++) {
        __syncthreads();
        *(float4*)(sA + ar * 64 + aq) = pa;
        if (wact) *(float4*)(sW + wr * 32 + wq) = pw;
        __syncthreads();
        if (s + 1 < 16) {
            int k0 = (s + 1) << 4;
            pa = *(const float4*)(A + (k0 + ar) * 64 + aq);
            if (wact) pw = *(const float4*)(W + (k0 + wr) * 4096 + cb + wq);
        }
#pragma unroll
        for (int k = 0; k < 16; k++) {
            ull a = *(const ull*)(sA + k * 64 + bg2);
            float4 w = *(const float4*)(sW + k * 32 + cg4);
            fma2(acc[0], a, pack2(w.x, w.x));
            fma2(acc[1], a, pack2(w.y, w.y));
            fma2(acc[2], a, pack2(w.z, w.z));
            fma2(acc[3], a, pack2(w.w, w.w));
        }
    }
    __syncthreads();
}

// 16 contiguous cols, fixed K=256 (z projections). ldw param.
__device__ __forceinline__ void gemm_seg16(const float* __restrict__ A,
                                           const float* __restrict__ W,
                                           int ldw, int cb,
                                           float* sA, float* sW,
                                           ull (&acc)[2], int tid) {
    const int ar = tid >> 4, aq = (tid & 15) << 2;
    const bool wact = tid < 64;
    const int wr = tid >> 2, wq = (tid & 3) << 2;
    const int c = tid >> 4, bg4 = (tid & 15) << 2;
    float4 pa = *(const float4*)(A + ar * 64 + aq);
    float4 pw = make_float4(0.f, 0.f, 0.f, 0.f);
    if (wact) pw = *(const float4*)(W + wr * ldw + cb + wq);
    for (int s = 0; s < 16; s++) {
        __syncthreads();
        *(float4*)(sA + ar * 64 + aq) = pa;
        if (wact) *(float4*)(sW + wr * 16 + wq) = pw;
        __syncthreads();
        if (s + 1 < 16) {
            int k0 = (s + 1) << 4;
            pa = *(const float4*)(A + (k0 + ar) * 64 + aq);
            if (wact) pw = *(const float4*)(W + (k0 + wr) * ldw + cb + wq);
        }
#pragma unroll
        for (int k = 0; k < 16; k++) {
            ulonglong2 a = *(const ulonglong2*)(sA + k * 64 + bg4);
            float w = sW[k * 16 + c];
            ull wp = pack2(w, w);
            fma2(acc[0], a.x, wp);
            fma2(acc[1], a.y, wp);
        }
    }
    __syncthreads();
}

// ---------------- prologue kernels ------------------------------------------
__global__ void k_transpose(const float* __restrict__ strokes) {
    int idx = blockIdx.x * blockDim.x + threadIdx.x;
    if (idx >= NSEQ * B * IND) return;
    int t = idx / (B * IND);
    int r = idx - t * (B * IND);
    int b = r / IND;
    int k = r - b * IND;
    g_x[t][k][b] = strokes[idx];
}

__global__ void k_init(const float* __restrict__ z, const float* __restrict__ w,
                       const float* __restrict__ bias) {
    int idx = blockIdx.x * blockDim.x + threadIdx.x;
    int b = idx & 63;
    int col = idx >> 6;
    if (col >= 2560) return;
    float acc = bias[col];
#pragma unroll 4
    for (int k = 0; k < 128; k++) acc += z[b * 128 + k] * w[k * 2560 + col];
    float v = tanhf(acc);
    if (col < 1024)       g_h[col][b] = v;
    else if (col < 2048)  g_c[col - 1024][b] = v;
    else if (col < 2304)  g_hh[0][col - 2048][b] = v;
    else                  g_ch[col - 2304][b] = v;
}

// g_axp[t] = x_t @ Wx (all t in parallel)
__global__ void __launch_bounds__(256) k_pre_ax(const float* __restrict__ Wx) {
    __shared__ __align__(16) float sm[2048];
    int t = blockIdx.y, cb = blockIdx.x * 64, tid = threadIdx.x;
    ull acc[4][2] = {};
    gemm_seg64(&g_x[t][0][0], Wx, IND, 4096, cb,
               (float(*)[64])sm, (float(*)[64])(sm + 1024), acc, tid);
    int bg4 = (tid & 15) << 2, cg4 = (tid >> 4) << 2;
#pragma unroll
    for (int c = 0; c < 4; c++) {
        ulonglong2 v; v.x = acc[c][0]; v.y = acc[c][1];
        *(ulonglong2*)(&g_axp[t][cb + cg4 + c][bg4]) = v;
    }
}

// g_gxh[t] = x_t @ Wxh[0:IND] (x slice of hyper gate GEMM)
__global__ void __launch_bounds__(256) k_pre_gxh(const float* __restrict__ Wxh) {
    __shared__ __align__(16) float sm[2048];
    int t = blockIdx.y, cb = blockIdx.x * 64, tid = threadIdx.x;
    ull acc[4][2] = {};
    gemm_seg64(&g_x[t][0][0], Wxh, IND, 1024, cb,
               (float(*)[64])sm, (float(*)[64])(sm + 1024), acc, tid);
    int bg4 = (tid & 15) << 2, cg4 = (tid >> 4) << 2;
#pragma unroll
    for (int c = 0; c < 4; c++) {
        ulonglong2 v; v.x = acc[c][0]; v.y = acc[c][1];
        *(ulonglong2*)(&g_gxh[t][cb + cg4 + c][bg4]) = v;
    }
}

// ---------------- THE persistent recurrence kernel ---------------------------
__global__ void __launch_bounds__(256, 1) k_seq(
        const float* __restrict__ Wxh, const float* __restrict__ Whh,
        const float* __restrict__ bhy, const float* __restrict__ Wh,
        const float* __restrict__ Wzx, const float* __restrict__ bzx,
        const float* __restrict__ Wzh, const float* __restrict__ bzh,
        const float* __restrict__ Wzb, const float* __restrict__ b0,
        const float* __restrict__ Dx, const float* __restrict__ Dh,
        const float* __restrict__ Db) {
    __shared__ __align__(16) float sm[11776]; // 47KB, re-carved per phase
    const int bx = blockIdx.x;
    const int tid = threadIdx.x;
    const float* WxhH = Wxh + IND * 1024;

    for (int t = 0; t < NSEQ; t++) {
        const int cur = t & 1, nxt = cur ^ 1;

        // ================= phase A =================
        if (bx < 32) {
            // hyper tile: gates for j in [jbase, jbase+8), K = 1024 + 256
            float (*sA)[64] = (float(*)[64])sm;
            float (*sW)[32] = (float(*)[32])(sm + 1024);
            float (*sPre)[64] = (float(*)[64])(sm + 1536);
            const int jbase = bx * 8;
            const int bg4 = (tid & 15) << 2;
            const int cg = tid >> 4;
            ull acc[2][2];
#pragma unroll
            for (int cc = 0; cc < 2; cc++) {
                int c = cg * 2 + cc;
                int wcol = ((c >> 3) << 8) + jbase + (c & 7);
                ulonglong2 v = *(const ulonglong2*)(&g_gxh[t][wcol][bg4]);
                acc[cc][0] = v.x; acc[cc][1] = v.y;
            }
            gemm_seg32h(&g_h[0][0],       WxhH, H,  jbase, sA, sW, acc, tid);
            gemm_seg32h(&g_hh[cur][0][0], Whh,  HY, jbase, sA, sW, acc, tid);
#pragma unroll
            for (int cc = 0; cc < 2; cc++) {
                int c = cg * 2 + cc;
                int g = c >> 3, jl = c & 7;
                float bv = bhy[(g << 8) + jbase + jl];
                ull bp = pack2(bv, bv);
                ulonglong2 v;
                v.x = add2(acc[cc][0], bp);
                v.y = add2(acc[cc][1], bp);
                *(ulonglong2*)(&sPre[c][bg4]) = v;
            }
            __syncthreads();
#pragma unroll
            for (int r = 0; r < 2; r++) {
                int idx = tid + (r << 8);
                int jl = idx >> 6, b = idx & 63;
                int jg = jbase + jl;
                float iv = sPre[jl][b];
                float fv = sPre[8 + jl][b];
                float gv = sPre[16 + jl][b];
                float ov = sPre[24 + jl][b];
                float chv = sigf(fv) * g_ch[jg][b] + sigf(iv) * tanhf(gv);
                g_ch[jg][b] = chv;
                g_hh[nxt][jg][b] = sigf(ov) * tanhf(chv);
            }
        } else {
            // h @ Wh as 512 units: 128 col-tiles of 32 x split-K4 (K=256 each)
            int wid0 = bx - 32;
            int start = (wid0 < 48) ? wid0 * 5 : 240 + (wid0 - 48) * 4;
            int cnt = (wid0 < 48) ? 5 : 4;
            const int cg4 = (tid >> 5) << 2, bg2 = (tid & 31) << 1;
            for (int i = 0; i < cnt; i++) {
                int u = start + i;
                int ct = u >> 2, ks = u & 3;
                ull acc[4] = {};
                gemm_seg32w(&g_h[ks * 256][0], Wh + ks * 256 * 4096, ct * 32,
                            sm, sm + 1024, acc, tid);
#pragma unroll
                for (int c = 0; c < 4; c++)
                    *(ull*)(&g_ahp[ks][ct * 32 + cg4 + c][bg2]) = acc[c];
            }
        }
        grid_bar();

        // ================= phase B: z projections =================
        if (bx < 48) {
            int type = bx >> 4, cb = (bx & 15) * 16;
            const float* W = (type == 0) ? Wzx : (type == 1) ? Wzh : Wzb;
            ull acc[2] = {};
            gemm_seg16(&g_hh[nxt][0][0], W, 256, cb, sm, sm + 1024, acc, tid);
            int c = tid >> 4, bg4 = (tid & 15) << 2;
            int col = cb + c;
            float bv = (type == 0) ? bzx[col] : (type == 1) ? bzh[col] : 0.0f;
            ull bp = pack2(bv, bv);
            ulonglong2 v;
            v.x = add2(acc[0], bp);
            v.y = add2(acc[1], bp);
            *(ulonglong2*)(&g_z[type * 256 + col][bg4]) = v;
        }
        grid_bar();

        // ================= phase C: einsums + combine + main cell =================
        if (bx < 64) {
            float (*sZ)[4][8][64] = (float(*)[4][8][64])sm;        // 6144
            float (*sWD)[8][64]   = (float(*)[8][64])(sm + 6144);  // 1536
            float (*sPre)[16][64] = (float(*)[16][64])(sm + 7680); // 4096
            const int jt = bx;
            const int bg4 = (tid & 15) << 2;
            const int cg = tid >> 4;
            const int gate = cg >> 2;
            const int j4 = (cg & 3) << 2;

            ull sx[4][2] = {}, sh[4][2] = {}, sb[4][2] = {};

            for (int st = 0; st < 8; st++) {
                int f0 = st * 8;
                __syncthreads();
                for (int i = tid; i < 1536; i += 256) {
                    int b4 = (i & 15) << 2;
                    int rowi = i >> 4;
                    int fr = rowi & 7, g = (rowi >> 3) & 3, ty = rowi >> 5;
                    *(float4*)(&sZ[ty][g][fr][b4]) =
                        *(const float4*)(&g_z[ty * 256 + g * 64 + f0 + fr][b4]);
                }
                for (int i = tid; i < 384; i += 256) {
                    int c4 = (i & 15) << 2;
                    int rowi = i >> 4;
                    int fr = rowi & 7, ty = rowi >> 3;
                    int g = c4 >> 4, jl = c4 & 15;
                    const float* D = (ty == 0) ? Dx : (ty == 1) ? Dh : Db;
                    *(float4*)(&sWD[ty][fr][c4]) =
                        *(const float4*)(D + (g * F + f0 + fr) * H + jt * 16 + jl);
                }
                __syncthreads();
#pragma unroll
                for (int k = 0; k < 8; k++) {
                    ulonglong2 azx = *(const ulonglong2*)(&sZ[0][gate][k][bg4]);
                    ulonglong2 azh = *(const ulonglong2*)(&sZ[1][gate][k][bg4]);
                    ulonglong2 azb = *(const ulonglong2*)(&sZ[2][gate][k][bg4]);
                    float4 wx = *(const float4*)(&sWD[0][k][cg * 4]);
                    float4 wh = *(const float4*)(&sWD[1][k][cg * 4]);
                    float4 wb = *(const float4*)(&sWD[2][k][cg * 4]);
#pragma unroll
                    for (int c = 0; c < 4; c++) {
                        float wxc = (c == 0) ? wx.x : (c == 1) ? wx.y : (c == 2) ? wx.z : wx.w;
                        float whc = (c == 0) ? wh.x : (c == 1) ? wh.y : (c == 2) ? wh.z : wh.w;
                        float wbc = (c == 0) ? wb.x : (c == 1) ? wb.y : (c == 2) ? wb.z : wb.w;
                        ull wxp = pack2(wxc, wxc), whp = pack2(whc, whc), wbp = pack2(wbc, wbc);
                        fma2(sx[c][0], azx.x, wxp); fma2(sx[c][1], azx.y, wxp);
                        fma2(sh[c][0], azh.x, whp); fma2(sh[c][1], azh.y, whp);
                        fma2(sb[c][0], azb.x, wbp); fma2(sb[c][1], azb.y, wbp);
                    }
                }
            }

#pragma unroll
            for (int c = 0; c < 4; c++) {
                int jglob = jt * 16 + j4 + c;
                int col = gate * 1024 + jglob;
                ulonglong2 ax = *(const ulonglong2*)(&g_axp[t][col][bg4]);
                ulonglong2 a0 = *(const ulonglong2*)(&g_ahp[0][col][bg4]);
                ulonglong2 a1 = *(const ulonglong2*)(&g_ahp[1][col][bg4]);
                ulonglong2 a2 = *(const ulonglong2*)(&g_ahp[2][col][bg4]);
                ulonglong2 a3 = *(const ulonglong2*)(&g_ahp[3][col][bg4]);
                ull ahx = add2(add2(a0.x, a1.x), add2(a2.x, a3.x));
                ull ahy = add2(add2(a0.y, a1.y), add2(a2.y, a3.y));
                float bv = b0[gate * 1024 + jglob];
                ull bp = pack2(bv, bv);
                ull p0 = mul2(sx[c][0], ax.x); fma2(p0, sh[c][0], ahx);
                p0 = add2(p0, sb[c][0]); p0 = add2(p0, bp);
                ull p1 = mul2(sx[c][1], ax.y); fma2(p1, sh[c][1], ahy);
                p1 = add2(p1, sb[c][1]); p1 = add2(p1, bp);
                ulonglong2 v; v.x = p0; v.y = p1;
                *(ulonglong2*)(&sPre[gate][j4 + c][bg4]) = v;
            }
            __syncthreads();

#pragma unroll
            for (int r = 0; r < 4; r++) {
                int idx = tid + (r << 8);
                int jl = idx >> 6, b = idx & 63;
                int jg = jt * 16 + jl;
                float iv = sPre[0][jl][b];
                float fv = sPre[1][jl][b];
                float gv = sPre[2][jl][b];
                float ov = sPre[3][jl][b];
                float cv = sigf(fv) * g_c[jg][b] + sigf(iv) * tanhf(gv);
                g_c[jg][b] = cv;
                float hn = sigf(ov) * tanhf(cv);
                g_h[jg][b] = hn;
                g_outs[t][jg][b] = hn;
            }
        }
        grid_bar();
    }
}

// ---------------- epilogue ---------------------------------------------------
__global__ void __launch_bounds__(256) k_proj(const float* __restrict__ Wp,
                                              const float* __restrict__ bp) {
    __shared__ __align__(16) float smem[2048];
    float (*sA)[64] = (float(*)[64])smem;
    float (*sW)[64] = (float(*)[64])(smem + 1024);
    int t = blockIdx.y;
    int cb = blockIdx.x * 64;
    int tid = threadIdx.x;
    const float* A = &g_outs[t][0][0];
    const int row = tid >> 4;
    const int q4 = (tid & 15) << 2;
    const int bg4 = (tid & 15) << 2;
    const int cg4 = (tid >> 4) << 2;
    ull acc[4][2] = {};

    float4 pa = *(const float4*)(A + row * 64 + q4);
    float4 pw;
    {
        const float* wr = Wp + row * OUTD + cb + q4;
        pw.x = (cb + q4 + 0 < OUTD) ? wr[0] : 0.f;
        pw.y = (cb + q4 + 1 < OUTD) ? wr[1] : 0.f;
        pw.z = (cb + q4 + 2 < OUTD) ? wr[2] : 0.f;
        pw.w = (cb + q4 + 3 < OUTD) ? wr[3] : 0.f;
    }
    for (int s = 0; s < 64; s++) {
        __syncthreads();
        *(float4*)(&sA[row][q4]) = pa;
        *(float4*)(&sW[row][q4]) = pw;
        __syncthreads();
        if (s + 1 < 64) {
            int kn = (s + 1) * 16 + row;
            pa = *(const float4*)(A + kn * 64 + q4);
            const float* wr = Wp + kn * OUTD + cb + q4;
            pw.x = (cb + q4 + 0 < OUTD) ? wr[0] : 0.f;
            pw.y = (cb + q4 + 1 < OUTD) ? wr[1] : 0.f;
            pw.z = (cb + q4 + 2 < OUTD) ? wr[2] : 0.f;
            pw.w = (cb + q4 + 3 < OUTD) ? wr[3] : 0.f;
        }
#pragma unroll
        for (int k = 0; k < 16; k++) {
            ulonglong2 a = *(const ulonglong2*)(&sA[k][bg4]);
            float4 w = *(const float4*)(&sW[k][cg4]);
            ull w0 = pack2(w.x, w.x), w1 = pack2(w.y, w.y);
            ull w2 = pack2(w.z, w.z), w3 = pack2(w.w, w.w);
            fma2(acc[0][0], a.x, w0); fma2(acc[0][1], a.y, w0);
            fma2(acc[1][0], a.x, w1); fma2(acc[1][1], a.y, w1);
            fma2(acc[2][0], a.x, w2); fma2(acc[2][1], a.y, w2);
            fma2(acc[3][0], a.x, w3); fma2(acc[3][1], a.y, w3);
        }
    }
#pragma unroll
    for (int c = 0; c < 4; c++) {
        int col = cb + cg4 + c;
        if (col < OUTD) {
            float bv = bp[col];
            ull bpp = pack2(bv, bv);
            ulonglong2 v;
            v.x = add2(acc[c][0], bpp);
            v.y = add2(acc[c][1], bpp);
            *(ulonglong2*)(&g_dec[t][col][bg4]) = v;
        }
    }
}

__global__ void k_mdn(float* __restrict__ out) {
    int idx = blockIdx.x * blockDim.x + threadIdx.x;
    if (idx >= NSEQ * B * 21) return;
    int u = idx % 21;
    int r = idx / 21;
    int b = r & 63;
    int t = r >> 6;
    if (u < 20) {
        int m = u;
        int off = t * 20 * 64 + m * 64 + b;
        out[off] = 1.0f;
        out[163840 + off] = g_dec[t][6 * m + 1][b];
        out[327680 + off] = g_dec[t][6 * m + 2][b];
        out[491520 + off] = expf(g_dec[t][6 * m + 3][b]);
        out[655360 + off] = expf(g_dec[t][6 * m + 4][b]);
        out[819200 + off] = tanhf(g_dec[t][6 * m + 5][b]);
    } else {
        float p0 = g_dec[t][120][b], p1 = g_dec[t][121][b], p2 = g_dec[t][122][b];
        float mx = fmaxf(p0, fmaxf(p1, p2));
        float e0 = expf(p0 - mx), e1 = expf(p1 - mx), e2 = expf(p2 - mx);
        float s = e0 + e1 + e2;
        int base = 983040 + t * (B * 3) + b * 3;
        out[base + 0] = e0 / s;
        out[base + 1] = e1 / s;
        out[base + 2] = e2 / s;
    }
}

// ---------------- host driver ------------------------------------------------
extern "C" void kernel_launch(void* const* d_in, const int* in_sizes, int n_in,
                              void* d_out, int out_size) {
    const float* z        = (const float*)d_in[0];
    const float* strokes  = (const float*)d_in[1];
    const float* fc_in_w  = (const float*)d_in[2];
    const float* fc_in_b  = (const float*)d_in[3];
    const float* fc_proj_w= (const float*)d_in[4];
    const float* fc_proj_b= (const float*)d_in[5];
    const float* Wx       = (const float*)d_in[6];
    const float* Wh       = (const float*)d_in[7];
    const float* b0       = (const float*)d_in[8];
    const float* Wxh      = (const float*)d_in[9];
    const float* Whh      = (const float*)d_in[10];
    const float* bhy      = (const float*)d_in[11];
    const float* Wzx      = (const float*)d_in[12];
    const float* bzx      = (const float*)d_in[13];
    const float* Wzh      = (const float*)d_in[14];
    const float* bzh      = (const float*)d_in[15];
    const float* Wzb      = (const float*)d_in[16];
    const float* Dx       = (const float*)d_in[17];
    const float* Dh       = (const float*)d_in[18];
    const float* Db       = (const float*)d_in[19];
    float* out = (float*)d_out;

    k_transpose<<<(NSEQ * B * IND + 255) / 256, 256>>>(strokes);
    k_init<<<(B * 2560 + 255) / 256, 256>>>(z, fc_in_w, fc_in_b);
    k_pre_ax<<<dim3(64, NSEQ), 256>>>(Wx);
    k_pre_gxh<<<dim3(16, NSEQ), 256>>>(Wxh);

    k_seq<<<GRID, 256>>>(Wxh, Whh, bhy, Wh, Wzx, bzx, Wzh, bzh, Wzb,
                         b0, Dx, Dh, Db);

    dim3 pg(2, NSEQ);
    k_proj<<<pg, 256>>>(fc_proj_w, fc_proj_b);
    k_mdn<<<(NSEQ * B * 21 + 255) / 256, 256>>>(out);
}

// round 9
// speedup vs baseline: 1.5416x; 1.5416x over previous
#include <cuda_runtime.h>
#include <math.h>
#include <stdint.h>

typedef unsigned long long ull;

#define B 64
#define H 1024
#define HY 256
#define F 64
#define IND 133
#define NSEQ 128
#define OUTD 123
#define GRID 148

// ---------------- persistent device state ----------------------------------
__device__ __align__(16) float g_h[H][B];
__device__ __align__(16) float g_c[H][B];
__device__ __align__(16) float g_hh[2][HY][B];
__device__ __align__(16) float g_ch[HY][B];
__device__ __align__(16) float g_z[3 * HY][B];
__device__ __align__(16) float g_ahp[4][4 * H][B];      // h@Wh split-K partials
__device__ __align__(16) float g_x[NSEQ][IND][B];
__device__ __align__(16) float g_axp[NSEQ][4 * H][B];   // precomputed x@Wx
__device__ __align__(16) float g_gxh[NSEQ][4 * HY][B];  // precomputed x@Wxh(x-rows)
__device__ __align__(16) float g_outs[NSEQ][H][B];
__device__ __align__(16) float g_dec[NSEQ][OUTD][B];
__device__ unsigned g_bar_count;
__device__ unsigned g_bar_gen;

__device__ __forceinline__ float sigf(float x) { return 1.0f / (1.0f + expf(-x)); }

__device__ __forceinline__ void fma2(ull& d, ull a, ull b) {
    asm("fma.rn.f32x2 %0, %1, %2, %0;" : "+l"(d) : "l"(a), "l"(b));
}
__device__ __forceinline__ ull mul2(ull a, ull b) {
    ull d; asm("mul.rn.f32x2 %0, %1, %2;" : "=l"(d) : "l"(a), "l"(b)); return d;
}
__device__ __forceinline__ ull add2(ull a, ull b) {
    ull d; asm("add.rn.f32x2 %0, %1, %2;" : "=l"(d) : "l"(a), "l"(b)); return d;
}
__device__ __forceinline__ ull pack2(float x, float y) {
    ull r; asm("mov.b64 %0, {%1, %2};" : "=l"(r) : "f"(x), "f"(y)); return r;
}

// ---------------- cp.async helpers ------------------------------------------
__device__ __forceinline__ void cpa16(void* dst, const void* src) {
    unsigned d = (unsigned)__cvta_generic_to_shared(dst);
    asm volatile("cp.async.cg.shared.global [%0], [%1], 16;" :: "r"(d), "l"(src));
}
__device__ __forceinline__ void cpa_commit() {
    asm volatile("cp.async.commit_group;");
}
template<int N>
__device__ __forceinline__ void cpa_wait() {
    asm volatile("cp.async.wait_group %0;" :: "n"(N));
}

// ---------------- grid-wide barrier (all blocks co-resident) ----------------
__device__ __forceinline__ void grid_bar() {
    __syncthreads();
    if (threadIdx.x == 0) {
        unsigned gen = *(volatile unsigned*)&g_bar_gen;
        __threadfence();
        unsigned arr = atomicAdd(&g_bar_count, 1u);
        if (arr == GRID - 1) {
            *(volatile unsigned*)&g_bar_count = 0u;
            __threadfence();
            *(volatile unsigned*)&g_bar_gen = gen + 1u;
        } else {
            while (*(volatile unsigned*)&g_bar_gen == gen) {}
        }
        __threadfence();
    }
    __syncthreads();
}

// ---------------- double-buffered 32-col GEMM core --------------------------
// acc[4] (+=): cols cb..cb+31 (thread: cols cg4..cg4+3 where cg4=(tid>>5)<<2,
// batch pair bg2=(tid&31)<<1), K = 32*nst over A[k][64].
// GATHER: W cols are 4 gate-strided groups of 8 (cb = jbase).
// smem: sA = sm[0..4096), sW = sm[4096..6144).
template<bool GATHER>
__device__ __forceinline__ void mm32(const float* __restrict__ A,
                                     const float* __restrict__ W,
                                     int ldw, int cb, int nst,
                                     float* sm, ull (&acc)[4], int tid) {
    float* sA = sm;
    float* sW = sm + 4096;
    const int ar  = tid >> 4;
    const int ac4 = (tid & 15) << 2;
    const int wr  = tid >> 3;
    const int wq  = tid & 7;
    const int cg4 = (tid >> 5) << 2;
    const int bg2 = (tid & 31) << 1;

    // stage 0 loads
    {
        cpa16(sA + ar * 64 + ac4, A + ar * 64 + ac4);
        cpa16(sA + (ar + 16) * 64 + ac4, A + (ar + 16) * 64 + ac4);
        const float* ws = GATHER
            ? (W + wr * ldw + ((wq >> 1) << 8) + cb + ((wq & 1) << 2))
            : (W + wr * ldw + cb + (wq << 2));
        cpa16(sW + wr * 32 + (wq << 2), ws);
        cpa_commit();
    }
    for (int s = 0; s < nst; s++) {
        int buf = s & 1;
        if (s + 1 < nst) {
            int k0 = (s + 1) << 5;
            float* dA = sA + (buf ^ 1) * 2048;
            float* dW = sW + (buf ^ 1) * 1024;
            cpa16(dA + ar * 64 + ac4, A + (k0 + ar) * 64 + ac4);
            cpa16(dA + (ar + 16) * 64 + ac4, A + (k0 + ar + 16) * 64 + ac4);
            const float* ws = GATHER
                ? (W + (k0 + wr) * ldw + ((wq >> 1) << 8) + cb + ((wq & 1) << 2))
                : (W + (k0 + wr) * ldw + cb + (wq << 2));
            cpa16(dW + wr * 32 + (wq << 2), ws);
            cpa_commit();
            cpa_wait<1>();
        } else {
            cpa_wait<0>();
        }
        __syncthreads();
        const float* cA = sA + buf * 2048;
        const float* cW = sW + buf * 1024;
#pragma unroll
        for (int k = 0; k < 32; k++) {
            ull a = *(const ull*)(cA + k * 64 + bg2);
            float4 w = *(const float4*)(cW + k * 32 + cg4);
            fma2(acc[0], a, pack2(w.x, w.x));
            fma2(acc[1], a, pack2(w.y, w.y));
            fma2(acc[2], a, pack2(w.z, w.z));
            fma2(acc[3], a, pack2(w.w, w.w));
        }
        __syncthreads();
    }
}

// ---------------- prologue kernels (unchanged, proven) -----------------------
__device__ __forceinline__ void gemm_seg64(const float* __restrict__ A,
                                           const float* __restrict__ W,
                                           int K, int ldw, int colbase,
                                           float (*sA)[64], float (*sW)[64],
                                           ull (&acc)[4][2], int tid) {
    const int row = tid >> 4;
    const int q4  = (tid & 15) << 2;
    const int bg4 = (tid & 15) << 2;
    const int cg4 = (tid >> 4) << 2;
    const int nst = (K + 15) >> 4;
    const float4 f40 = make_float4(0.f, 0.f, 0.f, 0.f);

    float4 pa = (row < K) ? *(const float4*)(A + row * 64 + q4) : f40;
    float4 pw = (row < K) ? *(const float4*)(W + row * ldw + colbase + q4) : f40;

    for (int s = 0; s < nst; s++) {
        __syncthreads();
        *(float4*)(&sA[row][q4]) = pa;
        *(float4*)(&sW[row][q4]) = pw;
        __syncthreads();
        if (s + 1 < nst) {
            int kn = (s + 1) * 16 + row;
            pa = (kn < K) ? *(const float4*)(A + kn * 64 + q4) : f40;
            pw = (kn < K) ? *(const float4*)(W + kn * ldw + colbase + q4) : f40;
        }
#pragma unroll
        for (int k = 0; k < 16; k++) {
            ulonglong2 a = *(const ulonglong2*)(&sA[k][bg4]);
            float4 w = *(const float4*)(&sW[k][cg4]);
            ull w0 = pack2(w.x, w.x), w1 = pack2(w.y, w.y);
            ull w2 = pack2(w.z, w.z), w3 = pack2(w.w, w.w);
            fma2(acc[0][0], a.x, w0); fma2(acc[0][1], a.y, w0);
            fma2(acc[1][0], a.x, w1); fma2(acc[1][1], a.y, w1);
            fma2(acc[2][0], a.x, w2); fma2(acc[2][1], a.y, w2);
            fma2(acc[3][0], a.x, w3); fma2(acc[3][1], a.y, w3);
        }
    }
    __syncthreads();
}

__global__ void k_transpose(const float* __restrict__ strokes) {
    int idx = blockIdx.x * blockDim.x + threadIdx.x;
    if (idx >= NSEQ * B * IND) return;
    int t = idx / (B * IND);
    int r = idx - t * (B * IND);
    int b = r / IND;
    int k = r - b * IND;
    g_x[t][k][b] = strokes[idx];
}

__global__ void k_init(const float* __restrict__ z, const float* __restrict__ w,
                       const float* __restrict__ bias) {
    int idx = blockIdx.x * blockDim.x + threadIdx.x;
    int b = idx & 63;
    int col = idx >> 6;
    if (col >= 2560) return;
    float acc = bias[col];
#pragma unroll 4
    for (int k = 0; k < 128; k++) acc += z[b * 128 + k] * w[k * 2560 + col];
    float v = tanhf(acc);
    if (col < 1024)       g_h[col][b] = v;
    else if (col < 2048)  g_c[col - 1024][b] = v;
    else if (col < 2304)  g_hh[0][col - 2048][b] = v;
    else                  g_ch[col - 2304][b] = v;
}

__global__ void __launch_bounds__(256) k_pre_ax(const float* __restrict__ Wx) {
    __shared__ __align__(16) float sm[2048];
    int t = blockIdx.y, cb = blockIdx.x * 64, tid = threadIdx.x;
    ull acc[4][2] = {};
    gemm_seg64(&g_x[t][0][0], Wx, IND, 4096, cb,
               (float(*)[64])sm, (float(*)[64])(sm + 1024), acc, tid);
    int bg4 = (tid & 15) << 2, cg4 = (tid >> 4) << 2;
#pragma unroll
    for (int c = 0; c < 4; c++) {
        ulonglong2 v; v.x = acc[c][0]; v.y = acc[c][1];
        *(ulonglong2*)(&g_axp[t][cb + cg4 + c][bg4]) = v;
    }
}

__global__ void __launch_bounds__(256) k_pre_gxh(const float* __restrict__ Wxh) {
    __shared__ __align__(16) float sm[2048];
    int t = blockIdx.y, cb = blockIdx.x * 64, tid = threadIdx.x;
    ull acc[4][2] = {};
    gemm_seg64(&g_x[t][0][0], Wxh, IND, 1024, cb,
               (float(*)[64])sm, (float(*)[64])(sm + 1024), acc, tid);
    int bg4 = (tid & 15) << 2, cg4 = (tid >> 4) << 2;
#pragma unroll
    for (int c = 0; c < 4; c++) {
        ulonglong2 v; v.x = acc[c][0]; v.y = acc[c][1];
        *(ulonglong2*)(&g_gxh[t][cb + cg4 + c][bg4]) = v;
    }
}

// ---------------- THE persistent recurrence kernel ---------------------------
__global__ void __launch_bounds__(256, 1) k_seq(
        const float* __restrict__ Wxh, const float* __restrict__ Whh,
        const float* __restrict__ bhy, const float* __restrict__ Wh,
        const float* __restrict__ Wzx, const float* __restrict__ bzx,
        const float* __restrict__ Wzh, const float* __restrict__ bzh,
        const float* __restrict__ Wzb, const float* __restrict__ b0,
        const float* __restrict__ Dx, const float* __restrict__ Dh,
        const float* __restrict__ Db) {
    // union: phase A/B use [0,6144) for mm32; phase C uses
    // sZ [0,6144), sWD [6144,7680), sPre [7680,11776)  -> 47KB
    __shared__ __align__(16) float sm[11776];
    const int bx = blockIdx.x;
    const int tid = threadIdx.x;
    const float* WxhH = Wxh + IND * 1024;

    const int cg4 = (tid >> 5) << 2;
    const int bg2 = (tid & 31) << 1;

    for (int t = 0; t < NSEQ; t++) {
        const int cur = t & 1, nxt = cur ^ 1;

        // ================= phase A: hyper (32 blocks) || h@Wh (116 blocks) ===
        if (bx < 32) {
            const int jbase = bx * 8;
            ull acc[4];
#pragma unroll
            for (int i = 0; i < 4; i++) {
                int c = cg4 + i;
                acc[i] = *(const ull*)(&g_gxh[t][((c >> 3) << 8) + jbase + (c & 7)][bg2]);
            }
            mm32<true>(&g_h[0][0],       WxhH, 1024, jbase, 32, sm, acc, tid);
            mm32<true>(&g_hh[cur][0][0], Whh,  1024, jbase, 8,  sm, acc, tid);

            float* sPre = sm;  // 2048 floats (free after mm32)
#pragma unroll
            for (int i = 0; i < 4; i++) {
                int c = cg4 + i;
                float bv = bhy[((c >> 3) << 8) + jbase + (c & 7)];
                *(ull*)(&sPre[c * 64 + bg2]) = add2(acc[i], pack2(bv, bv));
            }
            __syncthreads();
#pragma unroll
            for (int r = 0; r < 2; r++) {
                int idx = tid + (r << 8);
                int jl = idx >> 6, b = idx & 63;
                int jg = jbase + jl;
                float iv = sPre[jl * 64 + b];
                float fv = sPre[(8 + jl) * 64 + b];
                float gv = sPre[(16 + jl) * 64 + b];
                float ov = sPre[(24 + jl) * 64 + b];
                float chv = sigf(fv) * g_ch[jg][b] + sigf(iv) * tanhf(gv);
                g_ch[jg][b] = chv;
                g_hh[nxt][jg][b] = sigf(ov) * tanhf(chv);
            }
        } else {
            // h @ Wh : 512 units of (32 cols, K=256). 48 blocks x5, 68 blocks x4.
            int w0 = bx - 32;
            int start = (w0 < 48) ? w0 * 5 : 240 + (w0 - 48) * 4;
            int cnt = (w0 < 48) ? 5 : 4;
            for (int i = 0; i < cnt; i++) {
                int u = start + i;
                int ct = u >> 2, ks = u & 3;
                ull acc[4] = {};
                mm32<false>(&g_h[ks * 256][0], Wh + ks * 256 * 4096, 4096,
                            ct * 32, 8, sm, acc, tid);
#pragma unroll
                for (int c = 0; c < 4; c++)
                    *(ull*)(&g_ahp[ks][ct * 32 + cg4 + c][bg2]) = acc[c];
            }
        }
        grid_bar();

        // ================= phase B: z projections (24 blocks) ================
        if (bx < 24) {
            int type = bx >> 3, cb = (bx & 7) * 32;
            const float* W = (type == 0) ? Wzx : (type == 1) ? Wzh : Wzb;
            ull acc[4] = {};
            mm32<false>(&g_hh[nxt][0][0], W, 256, cb, 8, sm, acc, tid);
#pragma unroll
            for (int c = 0; c < 4; c++) {
                int col = cb + cg4 + c;
                float bv = (type == 0) ? bzx[col] : (type == 1) ? bzh[col] : 0.0f;
                *(ull*)(&g_z[type * 256 + col][bg2]) = add2(acc[c], pack2(bv, bv));
            }
        }
        grid_bar();

        // ================= phase C: einsums + combine + cell (64 blocks) =====
        if (bx < 64) {
            const int jt = bx;
            const int bg4 = (tid & 15) << 2;
            const int cg16 = tid >> 4;          // 0..15 -> 4 local cols
            const int gate = cg16 >> 2;
            const int j4 = (cg16 & 3) << 2;

            ull sx[4][2] = {}, sh[4][2] = {}, sb[4][2] = {};

            // stage loader: f-chunk of 4; sZ[ty][g][fr][64]  sWD[ty][fr][64]
            {
                int f0 = 0;
#pragma unroll
                for (int p = 0; p < 3; p++) {
                    int i = tid + (p << 8);
                    int b4 = (i & 15) << 2;
                    int r = i >> 4;
                    int fr = r & 3, g = (r >> 2) & 3, ty = r >> 4;
                    cpa16(sm + ((ty * 4 + g) * 4 + fr) * 64 + b4,
                          &g_z[ty * 256 + g * 64 + f0 + fr][b4]);
                }
                if (tid < 192) {
                    int ty = tid >> 6, rem = tid & 63;
                    int fr = rem >> 4, c4 = (rem & 15) << 2;
                    const float* D = (ty == 0) ? Dx : (ty == 1) ? Dh : Db;
                    cpa16(sm + 6144 + (ty * 4 + fr) * 64 + c4,
                          D + ((c4 >> 4) * 64 + f0 + fr) * 1024 + jt * 16 + (c4 & 15));
                }
                cpa_commit();
            }
            for (int st = 0; st < 16; st++) {
                int buf = st & 1;
                if (st + 1 < 16) {
                    int f0 = (st + 1) << 2;
                    float* dZ = sm + (buf ^ 1) * 3072;
                    float* dW = sm + 6144 + (buf ^ 1) * 768;
#pragma unroll
                    for (int p = 0; p < 3; p++) {
                        int i = tid + (p << 8);
                        int b4 = (i & 15) << 2;
                        int r = i >> 4;
                        int fr = r & 3, g = (r >> 2) & 3, ty = r >> 4;
                        cpa16(dZ + ((ty * 4 + g) * 4 + fr) * 64 + b4,
                              &g_z[ty * 256 + g * 64 + f0 + fr][b4]);
                    }
                    if (tid < 192) {
                        int ty = tid >> 6, rem = tid & 63;
                        int fr = rem >> 4, c4 = (rem & 15) << 2;
                        const float* D = (ty == 0) ? Dx : (ty == 1) ? Dh : Db;
                        cpa16(dW + (ty * 4 + fr) * 64 + c4,
                              D + ((c4 >> 4) * 64 + f0 + fr) * 1024 + jt * 16 + (c4 & 15));
                    }
                    cpa_commit();
                    cpa_wait<1>();
                } else {
                    cpa_wait<0>();
                }
                __syncthreads();
                const float* cZ = sm + buf * 3072;
                const float* cW = sm + 6144 + buf * 768;
#pragma unroll
                for (int k = 0; k < 4; k++) {
                    ulonglong2 azx = *(const ulonglong2*)(cZ + ((0 * 4 + gate) * 4 + k) * 64 + bg4);
                    ulonglong2 azh = *(const ulonglong2*)(cZ + ((1 * 4 + gate) * 4 + k) * 64 + bg4);
                    ulonglong2 azb = *(const ulonglong2*)(cZ + ((2 * 4 + gate) * 4 + k) * 64 + bg4);
                    float4 wx = *(const float4*)(cW + (0 * 4 + k) * 64 + cg16 * 4);
                    float4 wh = *(const float4*)(cW + (1 * 4 + k) * 64 + cg16 * 4);
                    float4 wb = *(const float4*)(cW + (2 * 4 + k) * 64 + cg16 * 4);
#pragma unroll
                    for (int c = 0; c < 4; c++) {
                        float wxc = (c == 0) ? wx.x : (c == 1) ? wx.y : (c == 2) ? wx.z : wx.w;
                        float whc = (c == 0) ? wh.x : (c == 1) ? wh.y : (c == 2) ? wh.z : wh.w;
                        float wbc = (c == 0) ? wb.x : (c == 1) ? wb.y : (c == 2) ? wb.z : wb.w;
                        ull wxp = pack2(wxc, wxc), whp = pack2(whc, whc), wbp = pack2(wbc, wbc);
                        fma2(sx[c][0], azx.x, wxp); fma2(sx[c][1], azx.y, wxp);
                        fma2(sh[c][0], azh.x, whp); fma2(sh[c][1], azh.y, whp);
                        fma2(sb[c][0], azb.x, wbp); fma2(sb[c][1], azb.y, wbp);
                    }
                }
                __syncthreads();
            }

            float* sPre = sm + 7680;  // 4096 floats: [64 cols][64 batch]
#pragma unroll
            for (int c = 0; c < 4; c++) {
                int jglob = jt * 16 + j4 + c;
                int col = gate * 1024 + jglob;
                ulonglong2 ax = *(const ulonglong2*)(&g_axp[t][col][bg4]);
                ulonglong2 a0 = *(const ulonglong2*)(&g_ahp[0][col][bg4]);
                ulonglong2 a1 = *(const ulonglong2*)(&g_ahp[1][col][bg4]);
                ulonglong2 a2 = *(const ulonglong2*)(&g_ahp[2][col][bg4]);
                ulonglong2 a3 = *(const ulonglong2*)(&g_ahp[3][col][bg4]);
                ull ahx = add2(add2(a0.x, a1.x), add2(a2.x, a3.x));
                ull ahy = add2(add2(a0.y, a1.y), add2(a2.y, a3.y));
                float bv = b0[gate * 1024 + jglob];
                ull bp = pack2(bv, bv);
                ull p0 = mul2(sx[c][0], ax.x); fma2(p0, sh[c][0], ahx);
                p0 = add2(p0, sb[c][0]); p0 = add2(p0, bp);
                ull p1 = mul2(sx[c][1], ax.y); fma2(p1, sh[c][1], ahy);
                p1 = add2(p1, sb[c][1]); p1 = add2(p1, bp);
                *(ull*)(&sPre[(gate * 16 + j4 + c) * 64 + bg4]) = p0;
                *(ull*)(&sPre[(gate * 16 + j4 + c) * 64 + bg4 + 2]) = p1;
            }
            __syncthreads();

#pragma unroll
            for (int r = 0; r < 4; r++) {
                int idx = tid + (r << 8);
                int jl = idx >> 6, b = idx & 63;
                int jg = jt * 16 + jl;
                float iv = sPre[(0 * 16 + jl) * 64 + b];
                float fv = sPre[(1 * 16 + jl) * 64 + b];
                float gv = sPre[(2 * 16 + jl) * 64 + b];
                float ov = sPre[(3 * 16 + jl) * 64 + b];
                float cv = sigf(fv) * g_c[jg][b] + sigf(iv) * tanhf(gv);
                g_c[jg][b] = cv;
                float hn = sigf(ov) * tanhf(cv);
                g_h[jg][b] = hn;
                g_outs[t][jg][b] = hn;
            }
        }
        grid_bar();
    }
}

// ---------------- epilogue ---------------------------------------------------
__global__ void __launch_bounds__(256) k_proj(const float* __restrict__ Wp,
                                              const float* __restrict__ bp) {
    __shared__ __align__(16) float smem[2048];
    float (*sA)[64] = (float(*)[64])smem;
    float (*sW)[64] = (float(*)[64])(smem + 1024);
    int t = blockIdx.y;
    int cb = blockIdx.x * 64;
    int tid = threadIdx.x;
    const float* A = &g_outs[t][0][0];
    const int row = tid >> 4;
    const int q4 = (tid & 15) << 2;
    const int bg4 = (tid & 15) << 2;
    const int cg4 = (tid >> 4) << 2;
    ull acc[4][2] = {};

    float4 pa = *(const float4*)(A + row * 64 + q4);
    float4 pw;
    {
        const float* wr = Wp + row * OUTD + cb + q4;
        pw.x = (cb + q4 + 0 < OUTD) ? wr[0] : 0.f;
        pw.y = (cb + q4 + 1 < OUTD) ? wr[1] : 0.f;
        pw.z = (cb + q4 + 2 < OUTD) ? wr[2] : 0.f;
        pw.w = (cb + q4 + 3 < OUTD) ? wr[3] : 0.f;
    }
    for (int s = 0; s < 64; s++) {
        __syncthreads();
        *(float4*)(&sA[row][q4]) = pa;
        *(float4*)(&sW[row][q4]) = pw;
        __syncthreads();
        if (s + 1 < 64) {
            int kn = (s + 1) * 16 + row;
            pa = *(const float4*)(A + kn * 64 + q4);
            const float* wr = Wp + kn * OUTD + cb + q4;
            pw.x = (cb + q4 + 0 < OUTD) ? wr[0] : 0.f;
            pw.y = (cb + q4 + 1 < OUTD) ? wr[1] : 0.f;
            pw.z = (cb + q4 + 2 < OUTD) ? wr[2] : 0.f;
            pw.w = (cb + q4 + 3 < OUTD) ? wr[3] : 0.f;
        }
#pragma unroll
        for (int k = 0; k < 16; k++) {
            ulonglong2 a = *(const ulonglong2*)(&sA[k][bg4]);
            float4 w = *(const float4*)(&sW[k][cg4]);
            ull w0 = pack2(w.x, w.x), w1 = pack2(w.y, w.y);
            ull w2 = pack2(w.z, w.z), w3 = pack2(w.w, w.w);
            fma2(acc[0][0], a.x, w0); fma2(acc[0][1], a.y, w0);
            fma2(acc[1][0], a.x, w1); fma2(acc[1][1], a.y, w1);
            fma2(acc[2][0], a.x, w2); fma2(acc[2][1], a.y, w2);
            fma2(acc[3][0], a.x, w3); fma2(acc[3][1], a.y, w3);
        }
    }
#pragma unroll
    for (int c = 0; c < 4; c++) {
        int col = cb + cg4 + c;
        if (col < OUTD) {
            float bv = bp[col];
            ull bpp = pack2(bv, bv);
            ulonglong2 v;
            v.x = add2(acc[c][0], bpp);
            v.y = add2(acc[c][1], bpp);
            *(ulonglong2*)(&g_dec[t][col][bg4]) = v;
        }
    }
}

__global__ void k_mdn(float* __restrict__ out) {
    int idx = blockIdx.x * blockDim.x + threadIdx.x;
    if (idx >= NSEQ * B * 21) return;
    int u = idx % 21;
    int r = idx / 21;
    int b = r & 63;
    int t = r >> 6;
    if (u < 20) {
        int m = u;
        int off = t * 20 * 64 + m * 64 + b;
        out[off] = 1.0f;
        out[163840 + off] = g_dec[t][6 * m + 1][b];
        out[327680 + off] = g_dec[t][6 * m + 2][b];
        out[491520 + off] = expf(g_dec[t][6 * m + 3][b]);
        out[655360 + off] = expf(g_dec[t][6 * m + 4][b]);
        out[819200 + off] = tanhf(g_dec[t][6 * m + 5][b]);
    } else {
        float p0 = g_dec[t][120][b], p1 = g_dec[t][121][b], p2 = g_dec[t][122][b];
        float mx = fmaxf(p0, fmaxf(p1, p2));
        float e0 = expf(p0 - mx), e1 = expf(p1 - mx), e2 = expf(p2 - mx);
        float s = e0 + e1 + e2;
        int base = 983040 + t * (B * 3) + b * 3;
        out[base + 0] = e0 / s;
        out[base + 1] = e1 / s;
        out[base + 2] = e2 / s;
    }
}

// ---------------- host driver ------------------------------------------------
extern "C" void kernel_launch(void* const* d_in, const int* in_sizes, int n_in,
                              void* d_out, int out_size) {
    const float* z        = (const float*)d_in[0];
    const float* strokes  = (const float*)d_in[1];
    const float* fc_in_w  = (const float*)d_in[2];
    const float* fc_in_b  = (const float*)d_in[3];
    const float* fc_proj_w= (const float*)d_in[4];
    const float* fc_proj_b= (const float*)d_in[5];
    const float* Wx       = (const float*)d_in[6];
    const float* Wh       = (const float*)d_in[7];
    const float* b0       = (const float*)d_in[8];
    const float* Wxh      = (const float*)d_in[9];
    const float* Whh      = (const float*)d_in[10];
    const float* bhy      = (const float*)d_in[11];
    const float* Wzx      = (const float*)d_in[12];
    const float* bzx      = (const float*)d_in[13];
    const float* Wzh      = (const float*)d_in[14];
    const float* bzh      = (const float*)d_in[15];
    const float* Wzb      = (const float*)d_in[16];
    const float* Dx       = (const float*)d_in[17];
    const float* Dh       = (const float*)d_in[18];
    const float* Db       = (const float*)d_in[19];
    float* out = (float*)d_out;

    k_transpose<<<(NSEQ * B * IND + 255) / 256, 256>>>(strokes);
    k_init<<<(B * 2560 + 255) / 256, 256>>>(z, fc_in_w, fc_in_b);
    k_pre_ax<<<dim3(64, NSEQ), 256>>>(Wx);
    k_pre_gxh<<<dim3(16, NSEQ), 256>>>(Wxh);

    k_seq<<<GRID, 256>>>(Wxh, Whh, bhy, Wh, Wzx, bzx, Wzh, bzh, Wzb,
                         b0, Dx, Dh, Db);

    dim3 pg(2, NSEQ);
    k_proj<<<pg, 256>>>(fc_proj_w, fc_proj_b);
    k_mdn<<<(NSEQ * B * 21 + 255) / 256, 256>>>(out);
}